// round 6
// baseline (speedup 1.0000x reference)
#include <cuda_runtime.h>
#include <cuda_fp16.h>
#include <math.h>
#include <stdint.h>

#define NLEV 12
#define PRIME1 2654435761u
#define PRIME2 805459861u
#define HMASK ((1u << 21) - 1u)

struct LevelSpec {
    float    scale[NLEV];
    unsigned off[NLEV];
    unsigned res1[NLEV];    // res + 1 (dense stride base)
    unsigned hashed[NLEV];  // 0/1
};

__device__ float g_S[8192];     // per-line mean weighted L1
__device__ float g_part[256];   // conf-kernel block partials

// fp16 copy of table_op: one u32 = half2 (feature pair) per entry.
__device__ unsigned g_tb_h[17700000];

typedef unsigned long long u64;

// MLP weights in constant memory (filled per-launch by async D2D memcpy nodes).
__constant__ u64   c_w1o[768];
__constant__ u64   c_b1o[32];
__constant__ float c_w2o[64];
__constant__ float c_b2o[1];
__constant__ u64   c_w1c[768];
__constant__ u64   c_b1c[32];
__constant__ float c_w2c[64];
__constant__ float c_b2c[1];

// ---------- packed f32x2 helpers ----------
__device__ __forceinline__ u64 bcast_f32x2(float v) {
    u64 d;
    asm("mov.b64 %0, {%1, %1};" : "=l"(d) : "f"(v));
    return d;
}
__device__ __forceinline__ void fma_f32x2(u64& acc, u64 a, u64 b) {
    asm("fma.rn.f32x2 %0, %1, %2, %0;" : "+l"(acc) : "l"(a), "l"(b));
}
__device__ __forceinline__ float2 unpack_f32x2(u64 v) {
    float2 r;
    asm("mov.b64 {%0, %1}, %2;" : "=f"(r.x), "=f"(r.y) : "l"(v));
    return r;
}

// 24 -> 64(relu) -> 1 MLP, constant-memory weights, fully unrolled (LDCU path).
template <bool OP>
__device__ __forceinline__ float tiny_mlp(const float* feat) {
    u64 acc[32];
#pragma unroll
    for (int j = 0; j < 32; j++) acc[j] = OP ? c_b1o[j] : c_b1c[j];
#pragma unroll
    for (int k = 0; k < 24; k++) {
        u64 bf = bcast_f32x2(feat[k]);
#pragma unroll
        for (int j = 0; j < 32; j++) {
            u64 wv = OP ? c_w1o[k * 32 + j] : c_w1c[k * 32 + j];
            fma_f32x2(acc[j], bf, wv);
        }
    }
    float out = OP ? c_b2o[0] : c_b2c[0];
#pragma unroll
    for (int j = 0; j < 32; j++) {
        float2 h = unpack_f32x2(acc[j]);
        out += fmaxf(h.x, 0.0f) * (OP ? c_w2o[2 * j]     : c_w2c[2 * j]);
        out += fmaxf(h.y, 0.0f) * (OP ? c_w2o[2 * j + 1] : c_w2c[2 * j + 1]);
    }
    return out;
}

// ---------- table fp32 -> fp16 conversion (runs inside the graph) ----------
__global__ void convert_kernel(const float4* __restrict__ src, unsigned n4) {
    unsigned i = blockIdx.x * blockDim.x + threadIdx.x;
    if (i < n4) {
        float4 v = __ldg(src + i);
        __half2 a = __floats2half2_rn(v.x, v.y);
        __half2 b = __floats2half2_rn(v.z, v.w);
        g_tb_h[2 * i]     = *(unsigned*)&a;
        g_tb_h[2 * i + 1] = *(unsigned*)&b;
    }
}

__device__ __forceinline__ float2 h2f(unsigned raw) {
    __half2 h = *(__half2*)&raw;
    return __half22float2(h);
}

// Gather state for one 3-D level: 8 raw half2 words + fractional coords.
struct Gather3 {
    unsigned r[8];
    float ax, ay, az;
};

// Compute indices and ISSUE the 8 loads for level l (no consumption here).
// HASH is compile-time: for the fixed level formula, 3-D levels 0-3 are dense,
// 4-11 hashed.
template <int L>
__device__ __forceinline__ Gather3 gather_issue3(float u0, float u1, float u2,
                                                 const LevelSpec& sp) {
    Gather3 g;
    const float s = sp.scale[L];
    float px = u0 * s + 0.5f, py = u1 * s + 0.5f, pz = u2 * s + 0.5f;
    float fx = floorf(px), fy = floorf(py), fz = floorf(pz);
    g.ax = px - fx; g.ay = py - fy; g.az = pz - fz;
    unsigned ix = (unsigned)fx, iy = (unsigned)fy, iz = (unsigned)fz;

    unsigned id[8];
    if (L >= 4) {  // hashed
        unsigned hy0 = iy * PRIME1, hy1 = hy0 + PRIME1;
        unsigned hz0 = iz * PRIME2, hz1 = hz0 + PRIME2;
        unsigned a0 = ix ^ hy0, a1 = (ix + 1u) ^ hy0;
        unsigned a2 = ix ^ hy1, a3 = (ix + 1u) ^ hy1;
        id[0] = (a0 ^ hz0) & HMASK; id[1] = (a1 ^ hz0) & HMASK;
        id[2] = (a2 ^ hz0) & HMASK; id[3] = (a3 ^ hz0) & HMASK;
        id[4] = (a0 ^ hz1) & HMASK; id[5] = (a1 ^ hz1) & HMASK;
        id[6] = (a2 ^ hz1) & HMASK; id[7] = (a3 ^ hz1) & HMASK;
    } else {       // dense
        unsigned s1 = sp.res1[L], s2 = s1 * s1;
        unsigned base = ix + iy * s1 + iz * s2;
        id[0] = base;           id[1] = base + 1u;
        id[2] = base + s1;      id[3] = base + s1 + 1u;
        id[4] = base + s2;      id[5] = base + s2 + 1u;
        id[6] = base + s2 + s1; id[7] = base + s2 + s1 + 1u;
    }
    const unsigned off = sp.off[L];
#pragma unroll
    for (int c = 0; c < 8; c++) g.r[c] = __ldg(&g_tb_h[off + id[c]]);
    return g;
}

__device__ __forceinline__ void interp3(const Gather3& g, float* f2out) {
    float wx0 = 1.0f - g.ax, wy0 = 1.0f - g.ay, wz0 = 1.0f - g.az;
    float w00 = wx0 * wy0, w10 = g.ax * wy0, w01 = wx0 * g.ay, w11 = g.ax * g.ay;
    float c0 = w00 * wz0, c1 = w10 * wz0, c2 = w01 * wz0, c3 = w11 * wz0;
    float c4 = w00 * g.az, c5 = w10 * g.az, c6 = w01 * g.az, c7 = w11 * g.az;

    float2 v0 = h2f(g.r[0]), v1 = h2f(g.r[1]), v2 = h2f(g.r[2]), v3 = h2f(g.r[3]);
    float2 v4 = h2f(g.r[4]), v5 = h2f(g.r[5]), v6 = h2f(g.r[6]), v7 = h2f(g.r[7]);

    float fxo = c0 * v0.x; fxo += c1 * v1.x; fxo += c2 * v2.x; fxo += c3 * v3.x;
    fxo += c4 * v4.x; fxo += c5 * v5.x; fxo += c6 * v6.x; fxo += c7 * v7.x;
    float fyo = c0 * v0.y; fyo += c1 * v1.y; fyo += c2 * v2.y; fyo += c3 * v3.y;
    fyo += c4 * v4.y; fyo += c5 * v5.y; fyo += c6 * v6.y; fyo += c7 * v7.y;
    f2out[0] = fxo;
    f2out[1] = fyo;
}

// ========================== opacity path: B*P 3-D points ==========================
__global__ void __launch_bounds__(128, 4)
opacity_kernel(const float* __restrict__ pts, const float* __restrict__ gt,
               LevelSpec sp, int P) {
    __shared__ __align__(16) float s_pts[3072];
    __shared__ float s_red[128];

    const int tid = threadIdx.x;
    const int b = blockIdx.x;
    const float* ptb = pts + (size_t)b * P * 3;
    const float* gtb = gt + (size_t)b * P;

    {
        int n4 = (3 * P) / 4;
        const float4* src4 = (const float4*)ptb;
        for (int i = tid; i < n4; i += 128) ((float4*)s_pts)[i] = src4[i];
        for (int i = 4 * n4 + tid; i < 3 * P; i += 128) s_pts[i] = ptb[i];
    }
    __syncthreads();

    float lsum = 0.0f;
    for (int p = tid; p < P; p += 128) {
        float u0 = (s_pts[3 * p + 0] + 1.0f) * 0.5f;
        float u1 = (s_pts[3 * p + 1] + 1.0f) * 0.5f;
        float u2 = (s_pts[3 * p + 2] + 1.0f) * 0.5f;

        float feat[24];
        // software-pipelined in level pairs: issue 16 loads, then interpolate both
        {
            Gather3 gA, gB;
            gA = gather_issue3<0>(u0, u1, u2, sp);
            gB = gather_issue3<1>(u0, u1, u2, sp);
            interp3(gA, feat + 0);  interp3(gB, feat + 2);
            gA = gather_issue3<2>(u0, u1, u2, sp);
            gB = gather_issue3<3>(u0, u1, u2, sp);
            interp3(gA, feat + 4);  interp3(gB, feat + 6);
            gA = gather_issue3<4>(u0, u1, u2, sp);
            gB = gather_issue3<5>(u0, u1, u2, sp);
            interp3(gA, feat + 8);  interp3(gB, feat + 10);
            gA = gather_issue3<6>(u0, u1, u2, sp);
            gB = gather_issue3<7>(u0, u1, u2, sp);
            interp3(gA, feat + 12); interp3(gB, feat + 14);
            gA = gather_issue3<8>(u0, u1, u2, sp);
            gB = gather_issue3<9>(u0, u1, u2, sp);
            interp3(gA, feat + 16); interp3(gB, feat + 18);
            gA = gather_issue3<10>(u0, u1, u2, sp);
            gB = gather_issue3<11>(u0, u1, u2, sp);
            interp3(gA, feat + 20); interp3(gB, feat + 22);
        }

        float op = tiny_mlp<true>(feat);
        float lw = (p < 500) ? (4.0f / 3.0f) : (2.0f / 3.0f);
        lsum += fabsf(op - __ldg(gtb + p)) * lw;
    }

    s_red[tid] = lsum;
    __syncthreads();
#pragma unroll
    for (int st = 64; st > 0; st >>= 1) {
        if (tid < st) s_red[tid] += s_red[tid + st];
        __syncthreads();
    }
    if (tid == 0) g_S[b] = s_red[0] * (1.0f / (float)P);
}

// ========================== confidence path: B 2-D lines (fp32 table) ==========================
__global__ void __launch_bounds__(128, 4)
conf_kernel(const float* __restrict__ line, const float* __restrict__ table,
            LevelSpec sp, int B) {
    __shared__ float s_red[128];
    const int tid = threadIdx.x;

    const int i = blockIdx.x * 128 + tid;
    float val = 0.0f;
    if (i < B) {
        const float2* tb = (const float2*)table;
        float u0 = (__ldg(line + 2 * i) + 1.0f) * 0.5f;
        float u1 = (__ldg(line + 2 * i + 1) + 1.0f) * 0.5f;

        float feat[24];
#pragma unroll
        for (int l = 0; l < NLEV; l++) {
            const float s = sp.scale[l];
            float px = u0 * s + 0.5f, py = u1 * s + 0.5f;
            float fx = floorf(px), fy = floorf(py);
            float ax = px - fx, ay = py - fy;
            unsigned ix = (unsigned)fx, iy = (unsigned)fy;

            unsigned id[4];
            if (sp.hashed[l]) {
                unsigned hy0 = iy * PRIME1, hy1 = hy0 + PRIME1;
                id[0] = (ix ^ hy0) & HMASK; id[1] = ((ix + 1u) ^ hy0) & HMASK;
                id[2] = (ix ^ hy1) & HMASK; id[3] = ((ix + 1u) ^ hy1) & HMASK;
            } else {
                unsigned s1 = sp.res1[l];
                unsigned base = ix + iy * s1;
                id[0] = base;      id[1] = base + 1u;
                id[2] = base + s1; id[3] = base + s1 + 1u;
            }
            const unsigned off = sp.off[l];
            float2 v0 = __ldg(tb + off + id[0]);
            float2 v1 = __ldg(tb + off + id[1]);
            float2 v2 = __ldg(tb + off + id[2]);
            float2 v3 = __ldg(tb + off + id[3]);

            float wx0 = 1.0f - ax, wy0 = 1.0f - ay;
            float c0 = wx0 * wy0, c1 = ax * wy0, c2 = wx0 * ay, c3 = ax * ay;
            float fxo = c0 * v0.x; fxo += c1 * v1.x; fxo += c2 * v2.x; fxo += c3 * v3.x;
            float fyo = c0 * v0.y; fyo += c1 * v1.y; fyo += c2 * v2.y; fyo += c3 * v3.y;
            feat[2 * l] = fxo;
            feat[2 * l + 1] = fyo;
        }
        float conf = tiny_mlp<false>(feat);
        val = expf(-conf) * g_S[i] + conf;
    }

    s_red[tid] = val;
    __syncthreads();
#pragma unroll
    for (int st = 64; st > 0; st >>= 1) {
        if (tid < st) s_red[tid] += s_red[tid + st];
        __syncthreads();
    }
    if (tid == 0) g_part[blockIdx.x] = s_red[0];
}

__global__ void final_kernel(float* out, int nb, float invB) {
    __shared__ float sr[256];
    int t = threadIdx.x;
    sr[t] = (t < nb) ? g_part[t] : 0.0f;
    __syncthreads();
#pragma unroll
    for (int st = 128; st > 0; st >>= 1) {
        if (t < st) sr[t] += sr[t + st];
        __syncthreads();
    }
    if (t == 0) out[0] = sr[0] * invB;
}

// ---------- host: replicate _level_specs exactly (float64 math) ----------
static void make_specs(int D, LevelSpec* sp) {
    double f = pow(8192.0 / 16.0, 1.0 / 11.0);
    long long offset = 0;
    for (int l = 0; l < NLEV; l++) {
        double scale = 16.0 * pow(f, (double)l) - 1.0;
        long long res = (long long)ceil(scale) + 1;
        long long dense = 1;
        for (int d = 0; d < D; d++) dense *= (res + 1);
        long long params = dense;
        if (params > (1LL << 21)) params = (1LL << 21);
        params = ((params + 7) / 8) * 8;
        sp->scale[l]  = (float)scale;
        sp->off[l]    = (unsigned)offset;
        sp->res1[l]   = (unsigned)(res + 1);
        sp->hashed[l] = (dense > (1LL << 21)) ? 1u : 0u;
        offset += params;
    }
}

extern "C" void kernel_launch(void* const* d_in, const int* in_sizes, int n_in,
                              void* d_out, int out_size) {
    const float* line  = (const float*)d_in[0];
    const float* pts   = (const float*)d_in[1];
    const float* gt    = (const float*)d_in[2];
    const float* tconf = (const float*)d_in[3];
    const float* w1c   = (const float*)d_in[4];
    const float* b1c   = (const float*)d_in[5];
    const float* w2c   = (const float*)d_in[6];
    const float* b2c   = (const float*)d_in[7];
    const float* top   = (const float*)d_in[8];
    const float* w1o   = (const float*)d_in[9];
    const float* b1o   = (const float*)d_in[10];
    const float* w2o   = (const float*)d_in[11];
    const float* b2o   = (const float*)d_in[12];

    int B = in_sizes[0] / 2;
    int P = in_sizes[1] / (3 * B);
    unsigned tot3 = (unsigned)(in_sizes[8] / 2);   // entries in table_op

    LevelSpec sp3, sp2;
    make_specs(3, &sp3);
    make_specs(2, &sp2);

    // weights -> constant memory (D2D memcpy nodes; graph-capturable)
    cudaMemcpyToSymbolAsync(c_w1o, w1o, 1536 * sizeof(float), 0, cudaMemcpyDeviceToDevice);
    cudaMemcpyToSymbolAsync(c_b1o, b1o, 64 * sizeof(float),   0, cudaMemcpyDeviceToDevice);
    cudaMemcpyToSymbolAsync(c_w2o, w2o, 64 * sizeof(float),   0, cudaMemcpyDeviceToDevice);
    cudaMemcpyToSymbolAsync(c_b2o, b2o, sizeof(float),        0, cudaMemcpyDeviceToDevice);
    cudaMemcpyToSymbolAsync(c_w1c, w1c, 1536 * sizeof(float), 0, cudaMemcpyDeviceToDevice);
    cudaMemcpyToSymbolAsync(c_b1c, b1c, 64 * sizeof(float),   0, cudaMemcpyDeviceToDevice);
    cudaMemcpyToSymbolAsync(c_w2c, w2c, 64 * sizeof(float),   0, cudaMemcpyDeviceToDevice);
    cudaMemcpyToSymbolAsync(c_b2c, b2c, sizeof(float),        0, cudaMemcpyDeviceToDevice);

    // fp32 -> fp16 table conversion (2 entries per float4)
    unsigned n4 = tot3 / 2;
    convert_kernel<<<(n4 + 255) / 256, 256>>>((const float4*)top, n4);

    opacity_kernel<<<B, 128>>>(pts, gt, sp3, P);

    int nb = (B + 127) / 128;
    if (nb > 256) nb = 256;
    conf_kernel<<<nb, 128>>>(line, tconf, sp2, B);
    final_kernel<<<1, 256>>>((float*)d_out, nb, 1.0f / (float)B);
}

// round 7
// speedup vs baseline: 1.0633x; 1.0633x over previous
#include <cuda_runtime.h>
#include <cuda_fp16.h>
#include <math.h>
#include <stdint.h>

#define NLEV 12
#define PRIME1 2654435761u
#define PRIME2 805459861u
#define HMASK ((1u << 21) - 1u)

struct LevelSpec {
    float    scale[NLEV];
    unsigned off[NLEV];
    unsigned res1[NLEV];    // res + 1 (dense stride base)
    unsigned hashed[NLEV];  // 0/1
};

__device__ float g_S[8192];     // per-line mean weighted L1
__device__ float g_part[256];   // conf-kernel block partials

// fp16 copy of table_op: one u32 = half2 (feature pair) per entry.
__device__ __align__(8) unsigned g_tb_h[17700000];

typedef unsigned long long u64;

// MLP weights in constant memory (filled per-launch by async D2D memcpy nodes).
__constant__ u64   c_w1o[768];
__constant__ u64   c_b1o[32];
__constant__ float c_w2o[64];
__constant__ float c_b2o[1];
__constant__ u64   c_w1c[768];
__constant__ u64   c_b1c[32];
__constant__ float c_w2c[64];
__constant__ float c_b2c[1];

// ---------- packed f32x2 helpers ----------
__device__ __forceinline__ u64 bcast_f32x2(float v) {
    u64 d;
    asm("mov.b64 %0, {%1, %1};" : "=l"(d) : "f"(v));
    return d;
}
__device__ __forceinline__ void fma_f32x2(u64& acc, u64 a, u64 b) {
    asm("fma.rn.f32x2 %0, %1, %2, %0;" : "+l"(acc) : "l"(a), "l"(b));
}
__device__ __forceinline__ float2 unpack_f32x2(u64 v) {
    float2 r;
    asm("mov.b64 {%0, %1}, %2;" : "=f"(r.x), "=f"(r.y) : "l"(v));
    return r;
}

// 24 -> 64(relu) -> 1 MLP, constant-memory weights, fully unrolled (LDCU path).
template <bool OP>
__device__ __forceinline__ float tiny_mlp(const float* feat) {
    u64 acc[32];
#pragma unroll
    for (int j = 0; j < 32; j++) acc[j] = OP ? c_b1o[j] : c_b1c[j];
#pragma unroll
    for (int k = 0; k < 24; k++) {
        u64 bf = bcast_f32x2(feat[k]);
#pragma unroll
        for (int j = 0; j < 32; j++) {
            u64 wv = OP ? c_w1o[k * 32 + j] : c_w1c[k * 32 + j];
            fma_f32x2(acc[j], bf, wv);
        }
    }
    float out = OP ? c_b2o[0] : c_b2c[0];
#pragma unroll
    for (int j = 0; j < 32; j++) {
        float2 h = unpack_f32x2(acc[j]);
        out += fmaxf(h.x, 0.0f) * (OP ? c_w2o[2 * j]     : c_w2c[2 * j]);
        out += fmaxf(h.y, 0.0f) * (OP ? c_w2o[2 * j + 1] : c_w2c[2 * j + 1]);
    }
    return out;
}

// ---------- table fp32 -> fp16 conversion (runs inside the graph) ----------
__global__ void convert_kernel(const float4* __restrict__ src, unsigned n4) {
    unsigned i = blockIdx.x * blockDim.x + threadIdx.x;
    if (i < n4) {
        float4 v = __ldg(src + i);
        __half2 a = __floats2half2_rn(v.x, v.y);
        __half2 b = __floats2half2_rn(v.z, v.w);
        g_tb_h[2 * i]     = *(unsigned*)&a;
        g_tb_h[2 * i + 1] = *(unsigned*)&b;
    }
}

__device__ __forceinline__ float2 h2f(unsigned raw) {
    __half2 h = *(__half2*)&raw;
    return __half22float2(h);
}

// Fetch the x-corner pair (idx0, idx1) of one level.
// One aligned 8B load covers {idx0&~1, idx0|1}; when `ok`, idx1 == idx0^1 so
// the pair is complete (1 wavefront). Otherwise a predicated 4B load gets idx1.
__device__ __forceinline__ void fetch_pair(unsigned idx0, unsigned idx1, bool ok,
                                           unsigned& w0, unsigned& w1) {
    u64 both = __ldg((const u64*)&g_tb_h[idx0 & ~1u]);
    unsigned lo = (unsigned)both, hi = (unsigned)(both >> 32);
    bool odd = (idx0 & 1u) != 0u;
    w0 = odd ? hi : lo;
    if (ok) {
        w1 = odd ? lo : hi;
    } else {
        w1 = __ldg(&g_tb_h[idx1]);
    }
}

// ========================== opacity path: B*P 3-D points ==========================
__global__ void __launch_bounds__(128, 4)
opacity_kernel(const float* __restrict__ pts, const float* __restrict__ gt,
               LevelSpec sp, int P) {
    __shared__ __align__(16) float s_pts[3072];
    __shared__ float s_red[128];

    const int tid = threadIdx.x;
    const int b = blockIdx.x;
    const float* ptb = pts + (size_t)b * P * 3;
    const float* gtb = gt + (size_t)b * P;

    {
        int n4 = (3 * P) / 4;
        const float4* src4 = (const float4*)ptb;
        for (int i = tid; i < n4; i += 128) ((float4*)s_pts)[i] = src4[i];
        for (int i = 4 * n4 + tid; i < 3 * P; i += 128) s_pts[i] = ptb[i];
    }
    __syncthreads();

    float lsum = 0.0f;
    for (int p = tid; p < P; p += 128) {
        float u0 = (s_pts[3 * p + 0] + 1.0f) * 0.5f;
        float u1 = (s_pts[3 * p + 1] + 1.0f) * 0.5f;
        float u2 = (s_pts[3 * p + 2] + 1.0f) * 0.5f;

        float feat[24];
#pragma unroll
        for (int l = 0; l < NLEV; l++) {
            const float s = sp.scale[l];
            float px = u0 * s + 0.5f, py = u1 * s + 0.5f, pz = u2 * s + 0.5f;
            float fx = floorf(px), fy = floorf(py), fz = floorf(pz);
            float ax = px - fx, ay = py - fy, az = pz - fz;
            unsigned ix = (unsigned)fx, iy = (unsigned)fy, iz = (unsigned)fz;

            unsigned w[8];
            if (sp.hashed[l]) {
                const unsigned off = sp.off[l];
                unsigned hy0 = iy * PRIME1, hy1 = hy0 + PRIME1;
                unsigned hz0 = iz * PRIME2, hz1 = hz0 + PRIME2;
                unsigned a0 = ix ^ hy0, a1 = (ix + 1u) ^ hy0;
                unsigned a2 = ix ^ hy1, a3 = (ix + 1u) ^ hy1;
                unsigned i0 = off + ((a0 ^ hz0) & HMASK);
                unsigned i1 = off + ((a1 ^ hz0) & HMASK);
                unsigned i2 = off + ((a2 ^ hz0) & HMASK);
                unsigned i3 = off + ((a3 ^ hz0) & HMASK);
                unsigned i4 = off + ((a0 ^ hz1) & HMASK);
                unsigned i5 = off + ((a1 ^ hz1) & HMASK);
                unsigned i6 = off + ((a2 ^ hz1) & HMASK);
                unsigned i7 = off + ((a3 ^ hz1) & HMASK);
                bool ok = (ix & 1u) == 0u;   // then i1==i0^1 etc. (PRIMEs odd)
                fetch_pair(i0, i1, ok, w[0], w[1]);
                fetch_pair(i2, i3, ok, w[2], w[3]);
                fetch_pair(i4, i5, ok, w[4], w[5]);
                fetch_pair(i6, i7, ok, w[6], w[7]);
            } else {
                const unsigned off = sp.off[l];
                unsigned s1 = sp.res1[l], s2 = s1 * s1;
                unsigned base = off + ix + iy * s1 + iz * s2;
                unsigned i0 = base, i2 = base + s1, i4 = base + s2, i6 = base + s2 + s1;
                fetch_pair(i0, i0 + 1u, (i0 & 1u) == 0u, w[0], w[1]);
                fetch_pair(i2, i2 + 1u, (i2 & 1u) == 0u, w[2], w[3]);
                fetch_pair(i4, i4 + 1u, (i4 & 1u) == 0u, w[4], w[5]);
                fetch_pair(i6, i6 + 1u, (i6 & 1u) == 0u, w[6], w[7]);
            }

            float wx0 = 1.0f - ax, wy0 = 1.0f - ay, wz0 = 1.0f - az;
            float w00 = wx0 * wy0, w10 = ax * wy0, w01 = wx0 * ay, w11 = ax * ay;
            float c0 = w00 * wz0, c1 = w10 * wz0, c2 = w01 * wz0, c3 = w11 * wz0;
            float c4 = w00 * az,  c5 = w10 * az,  c6 = w01 * az,  c7 = w11 * az;

            float2 v0 = h2f(w[0]), v1 = h2f(w[1]), v2 = h2f(w[2]), v3 = h2f(w[3]);
            float2 v4 = h2f(w[4]), v5 = h2f(w[5]), v6 = h2f(w[6]), v7 = h2f(w[7]);

            float fxo = c0 * v0.x; fxo += c1 * v1.x; fxo += c2 * v2.x; fxo += c3 * v3.x;
            fxo += c4 * v4.x; fxo += c5 * v5.x; fxo += c6 * v6.x; fxo += c7 * v7.x;
            float fyo = c0 * v0.y; fyo += c1 * v1.y; fyo += c2 * v2.y; fyo += c3 * v3.y;
            fyo += c4 * v4.y; fyo += c5 * v5.y; fyo += c6 * v6.y; fyo += c7 * v7.y;
            feat[2 * l] = fxo;
            feat[2 * l + 1] = fyo;
        }

        float op = tiny_mlp<true>(feat);
        float lw = (p < 500) ? (4.0f / 3.0f) : (2.0f / 3.0f);
        lsum += fabsf(op - __ldg(gtb + p)) * lw;
    }

    s_red[tid] = lsum;
    __syncthreads();
#pragma unroll
    for (int st = 64; st > 0; st >>= 1) {
        if (tid < st) s_red[tid] += s_red[tid + st];
        __syncthreads();
    }
    if (tid == 0) g_S[b] = s_red[0] * (1.0f / (float)P);
}

// ========================== confidence path: B 2-D lines (fp32 table) ==========================
__global__ void __launch_bounds__(128, 4)
conf_kernel(const float* __restrict__ line, const float* __restrict__ table,
            LevelSpec sp, int B) {
    __shared__ float s_red[128];
    const int tid = threadIdx.x;

    const int i = blockIdx.x * 128 + tid;
    float val = 0.0f;
    if (i < B) {
        const float2* tb = (const float2*)table;
        float u0 = (__ldg(line + 2 * i) + 1.0f) * 0.5f;
        float u1 = (__ldg(line + 2 * i + 1) + 1.0f) * 0.5f;

        float feat[24];
#pragma unroll
        for (int l = 0; l < NLEV; l++) {
            const float s = sp.scale[l];
            float px = u0 * s + 0.5f, py = u1 * s + 0.5f;
            float fx = floorf(px), fy = floorf(py);
            float ax = px - fx, ay = py - fy;
            unsigned ix = (unsigned)fx, iy = (unsigned)fy;

            unsigned id[4];
            if (sp.hashed[l]) {
                unsigned hy0 = iy * PRIME1, hy1 = hy0 + PRIME1;
                id[0] = (ix ^ hy0) & HMASK; id[1] = ((ix + 1u) ^ hy0) & HMASK;
                id[2] = (ix ^ hy1) & HMASK; id[3] = ((ix + 1u) ^ hy1) & HMASK;
            } else {
                unsigned s1 = sp.res1[l];
                unsigned base = ix + iy * s1;
                id[0] = base;      id[1] = base + 1u;
                id[2] = base + s1; id[3] = base + s1 + 1u;
            }
            const unsigned off = sp.off[l];
            float2 v0 = __ldg(tb + off + id[0]);
            float2 v1 = __ldg(tb + off + id[1]);
            float2 v2 = __ldg(tb + off + id[2]);
            float2 v3 = __ldg(tb + off + id[3]);

            float wx0 = 1.0f - ax, wy0 = 1.0f - ay;
            float c0 = wx0 * wy0, c1 = ax * wy0, c2 = wx0 * ay, c3 = ax * ay;
            float fxo = c0 * v0.x; fxo += c1 * v1.x; fxo += c2 * v2.x; fxo += c3 * v3.x;
            float fyo = c0 * v0.y; fyo += c1 * v1.y; fyo += c2 * v2.y; fyo += c3 * v3.y;
            feat[2 * l] = fxo;
            feat[2 * l + 1] = fyo;
        }
        float conf = tiny_mlp<false>(feat);
        val = expf(-conf) * g_S[i] + conf;
    }

    s_red[tid] = val;
    __syncthreads();
#pragma unroll
    for (int st = 64; st > 0; st >>= 1) {
        if (tid < st) s_red[tid] += s_red[tid + st];
        __syncthreads();
    }
    if (tid == 0) g_part[blockIdx.x] = s_red[0];
}

__global__ void final_kernel(float* out, int nb, float invB) {
    __shared__ float sr[256];
    int t = threadIdx.x;
    sr[t] = (t < nb) ? g_part[t] : 0.0f;
    __syncthreads();
#pragma unroll
    for (int st = 128; st > 0; st >>= 1) {
        if (t < st) sr[t] += sr[t + st];
        __syncthreads();
    }
    if (t == 0) out[0] = sr[0] * invB;
}

// ---------- host: replicate _level_specs exactly (float64 math) ----------
static void make_specs(int D, LevelSpec* sp) {
    double f = pow(8192.0 / 16.0, 1.0 / 11.0);
    long long offset = 0;
    for (int l = 0; l < NLEV; l++) {
        double scale = 16.0 * pow(f, (double)l) - 1.0;
        long long res = (long long)ceil(scale) + 1;
        long long dense = 1;
        for (int d = 0; d < D; d++) dense *= (res + 1);
        long long params = dense;
        if (params > (1LL << 21)) params = (1LL << 21);
        params = ((params + 7) / 8) * 8;
        sp->scale[l]  = (float)scale;
        sp->off[l]    = (unsigned)offset;
        sp->res1[l]   = (unsigned)(res + 1);
        sp->hashed[l] = (dense > (1LL << 21)) ? 1u : 0u;
        offset += params;
    }
}

extern "C" void kernel_launch(void* const* d_in, const int* in_sizes, int n_in,
                              void* d_out, int out_size) {
    const float* line  = (const float*)d_in[0];
    const float* pts   = (const float*)d_in[1];
    const float* gt    = (const float*)d_in[2];
    const float* tconf = (const float*)d_in[3];
    const float* w1c   = (const float*)d_in[4];
    const float* b1c   = (const float*)d_in[5];
    const float* w2c   = (const float*)d_in[6];
    const float* b2c   = (const float*)d_in[7];
    const float* top   = (const float*)d_in[8];
    const float* w1o   = (const float*)d_in[9];
    const float* b1o   = (const float*)d_in[10];
    const float* w2o   = (const float*)d_in[11];
    const float* b2o   = (const float*)d_in[12];

    int B = in_sizes[0] / 2;
    int P = in_sizes[1] / (3 * B);
    unsigned tot3 = (unsigned)(in_sizes[8] / 2);   // entries in table_op

    LevelSpec sp3, sp2;
    make_specs(3, &sp3);
    make_specs(2, &sp2);

    // weights -> constant memory (D2D memcpy nodes; graph-capturable)
    cudaMemcpyToSymbolAsync(c_w1o, w1o, 1536 * sizeof(float), 0, cudaMemcpyDeviceToDevice);
    cudaMemcpyToSymbolAsync(c_b1o, b1o, 64 * sizeof(float),   0, cudaMemcpyDeviceToDevice);
    cudaMemcpyToSymbolAsync(c_w2o, w2o, 64 * sizeof(float),   0, cudaMemcpyDeviceToDevice);
    cudaMemcpyToSymbolAsync(c_b2o, b2o, sizeof(float),        0, cudaMemcpyDeviceToDevice);
    cudaMemcpyToSymbolAsync(c_w1c, w1c, 1536 * sizeof(float), 0, cudaMemcpyDeviceToDevice);
    cudaMemcpyToSymbolAsync(c_b1c, b1c, 64 * sizeof(float),   0, cudaMemcpyDeviceToDevice);
    cudaMemcpyToSymbolAsync(c_w2c, w2c, 64 * sizeof(float),   0, cudaMemcpyDeviceToDevice);
    cudaMemcpyToSymbolAsync(c_b2c, b2c, sizeof(float),        0, cudaMemcpyDeviceToDevice);

    // fp32 -> fp16 table conversion (2 entries per float4)
    unsigned n4 = tot3 / 2;
    convert_kernel<<<(n4 + 255) / 256, 256>>>((const float4*)top, n4);

    opacity_kernel<<<B, 128>>>(pts, gt, sp3, P);

    int nb = (B + 127) / 128;
    if (nb > 256) nb = 256;
    conf_kernel<<<nb, 128>>>(line, tconf, sp2, B);
    final_kernel<<<1, 256>>>((float*)d_out, nb, 1.0f / (float)B);
}

// round 8
// speedup vs baseline: 1.1056x; 1.0397x over previous
#include <cuda_runtime.h>
#include <cuda_fp16.h>
#include <math.h>
#include <stdint.h>

#define NLEV 12
#define PRIME1 2654435761u
#define PRIME2 805459861u
#define HMASK ((1u << 21) - 1u)

struct LevelSpec {
    float    scale[NLEV];
    unsigned off[NLEV];
    unsigned res1[NLEV];    // res + 1 (dense stride base)
    unsigned hashed[NLEV];  // 0/1
};

__device__ float g_S[8192];     // per-line mean weighted L1
__device__ float g_part[256];   // conf-kernel block partials

// fp16 copy of table_op: one u32 = half2 (feature pair) per entry.
__device__ __align__(8) unsigned g_tb_h[17700000];

typedef unsigned long long u64;

// MLP weights in constant memory (filled per-launch by async D2D memcpy nodes).
__constant__ u64   c_w1o[768];
__constant__ u64   c_b1o[32];
__constant__ float c_w2o[64];
__constant__ float c_b2o[1];
__constant__ u64   c_w1c[768];
__constant__ u64   c_b1c[32];
__constant__ float c_w2c[64];
__constant__ float c_b2c[1];

// ---------- packed f32x2 helpers ----------
__device__ __forceinline__ u64 bcast_f32x2(float v) {
    u64 d;
    asm("mov.b64 %0, {%1, %1};" : "=l"(d) : "f"(v));
    return d;
}
__device__ __forceinline__ void fma_f32x2(u64& acc, u64 a, u64 b) {
    asm("fma.rn.f32x2 %0, %1, %2, %0;" : "+l"(acc) : "l"(a), "l"(b));
}
__device__ __forceinline__ float2 unpack_f32x2(u64 v) {
    float2 r;
    asm("mov.b64 {%0, %1}, %2;" : "=f"(r.x), "=f"(r.y) : "l"(v));
    return r;
}

// 24 -> 64(relu) -> 1 MLP, constant-memory weights, fully unrolled (LDCU path).
template <bool OP>
__device__ __forceinline__ float tiny_mlp(const float* feat) {
    u64 acc[32];
#pragma unroll
    for (int j = 0; j < 32; j++) acc[j] = OP ? c_b1o[j] : c_b1c[j];
#pragma unroll
    for (int k = 0; k < 24; k++) {
        u64 bf = bcast_f32x2(feat[k]);
#pragma unroll
        for (int j = 0; j < 32; j++) {
            u64 wv = OP ? c_w1o[k * 32 + j] : c_w1c[k * 32 + j];
            fma_f32x2(acc[j], bf, wv);
        }
    }
    float out = OP ? c_b2o[0] : c_b2c[0];
#pragma unroll
    for (int j = 0; j < 32; j++) {
        float2 h = unpack_f32x2(acc[j]);
        out += fmaxf(h.x, 0.0f) * (OP ? c_w2o[2 * j]     : c_w2c[2 * j]);
        out += fmaxf(h.y, 0.0f) * (OP ? c_w2o[2 * j + 1] : c_w2c[2 * j + 1]);
    }
    return out;
}

// ---------- table fp32 -> fp16 conversion (runs inside the graph) ----------
__global__ void convert_kernel(const float4* __restrict__ src, unsigned n4) {
    unsigned i = blockIdx.x * blockDim.x + threadIdx.x;
    if (i < n4) {
        float4 v = __ldg(src + i);
        __half2 a = __floats2half2_rn(v.x, v.y);
        __half2 b = __floats2half2_rn(v.z, v.w);
        g_tb_h[2 * i]     = *(unsigned*)&a;
        g_tb_h[2 * i + 1] = *(unsigned*)&b;
    }
}

__device__ __forceinline__ float2 h2f(unsigned raw) {
    __half2 h = *(__half2*)&raw;
    return __half22float2(h);
}

// Branch-free predicated load: fires only when need != 0 (no BSSY/BSYNC).
__device__ __forceinline__ unsigned pred_ldg(unsigned need, const unsigned* p) {
    unsigned v = 0;
    asm("{ .reg .pred %%pp; setp.ne.u32 %%pp, %1, 0; @%%pp ld.global.nc.b32 %0, [%2]; }"
        : "+r"(v) : "r"(need), "l"(p));
    return v;
}

// Fetch x-corner pair for a hashed level. When ix is even, i1 == i0^1 and one
// aligned 8B load covers both corners; otherwise a predicated 4B load fills i1.
__device__ __forceinline__ void hpair(unsigned i0, unsigned i1, unsigned need_i1,
                                      unsigned& w0, unsigned& w1) {
    u64 both = __ldg((const u64*)&g_tb_h[i0 & ~1u]);
    unsigned lo = (unsigned)both, hi = (unsigned)(both >> 32);
    unsigned other = pred_ldg(need_i1, &g_tb_h[i1]);
    bool odd = (i0 & 1u) != 0u;
    w0 = odd ? hi : lo;
    unsigned partner = odd ? lo : hi;
    w1 = need_i1 ? other : partner;
}

// ========================== opacity path: B*P 3-D points ==========================
__global__ void __launch_bounds__(128, 4)
opacity_kernel(const float* __restrict__ pts, const float* __restrict__ gt,
               LevelSpec sp, int P) {
    __shared__ __align__(16) float s_pts[3072];
    __shared__ float s_red[128];

    const int tid = threadIdx.x;
    const int b = blockIdx.x;
    const float* ptb = pts + (size_t)b * P * 3;
    const float* gtb = gt + (size_t)b * P;

    {
        int n4 = (3 * P) / 4;
        const float4* src4 = (const float4*)ptb;
        for (int i = tid; i < n4; i += 128) ((float4*)s_pts)[i] = src4[i];
        for (int i = 4 * n4 + tid; i < 3 * P; i += 128) s_pts[i] = ptb[i];
    }
    __syncthreads();

    float lsum = 0.0f;
    for (int p = tid; p < P; p += 128) {
        float u0 = (s_pts[3 * p + 0] + 1.0f) * 0.5f;
        float u1 = (s_pts[3 * p + 1] + 1.0f) * 0.5f;
        float u2 = (s_pts[3 * p + 2] + 1.0f) * 0.5f;

        float feat[24];
#pragma unroll
        for (int l = 0; l < NLEV; l++) {
            const float s = sp.scale[l];
            float px = u0 * s + 0.5f, py = u1 * s + 0.5f, pz = u2 * s + 0.5f;
            float fx = floorf(px), fy = floorf(py), fz = floorf(pz);
            float ax = px - fx, ay = py - fy, az = pz - fz;
            unsigned ix = (unsigned)fx, iy = (unsigned)fy, iz = (unsigned)fz;

            float2 v0, v1, v2, v3, v4, v5, v6, v7;
            if (sp.hashed[l]) {
                const unsigned off = sp.off[l];
                unsigned hy0 = iy * PRIME1, hy1 = hy0 + PRIME1;
                unsigned hz0 = iz * PRIME2, hz1 = hz0 + PRIME2;
                unsigned a0 = ix ^ hy0, a1 = (ix + 1u) ^ hy0;
                unsigned a2 = ix ^ hy1, a3 = (ix + 1u) ^ hy1;
                unsigned i0 = off + ((a0 ^ hz0) & HMASK);
                unsigned i1 = off + ((a1 ^ hz0) & HMASK);
                unsigned i2 = off + ((a2 ^ hz0) & HMASK);
                unsigned i3 = off + ((a3 ^ hz0) & HMASK);
                unsigned i4 = off + ((a0 ^ hz1) & HMASK);
                unsigned i5 = off + ((a1 ^ hz1) & HMASK);
                unsigned i6 = off + ((a2 ^ hz1) & HMASK);
                unsigned i7 = off + ((a3 ^ hz1) & HMASK);
                unsigned need = ix & 1u;   // odd ix -> pair not adjacent
                unsigned w0, w1, w2, w3, w4, w5, w6, w7;
                hpair(i0, i1, need, w0, w1);
                hpair(i2, i3, need, w2, w3);
                hpair(i4, i5, need, w4, w5);
                hpair(i6, i7, need, w6, w7);
                v0 = h2f(w0); v1 = h2f(w1); v2 = h2f(w2); v3 = h2f(w3);
                v4 = h2f(w4); v5 = h2f(w5); v6 = h2f(w6); v7 = h2f(w7);
            } else {
                const unsigned off = sp.off[l];
                unsigned s1 = sp.res1[l], s2 = s1 * s1;
                unsigned base = off + ix + iy * s1 + iz * s2;
                v0 = h2f(__ldg(&g_tb_h[base]));
                v1 = h2f(__ldg(&g_tb_h[base + 1u]));
                v2 = h2f(__ldg(&g_tb_h[base + s1]));
                v3 = h2f(__ldg(&g_tb_h[base + s1 + 1u]));
                v4 = h2f(__ldg(&g_tb_h[base + s2]));
                v5 = h2f(__ldg(&g_tb_h[base + s2 + 1u]));
                v6 = h2f(__ldg(&g_tb_h[base + s2 + s1]));
                v7 = h2f(__ldg(&g_tb_h[base + s2 + s1 + 1u]));
            }

            float wx0 = 1.0f - ax, wy0 = 1.0f - ay, wz0 = 1.0f - az;
            float w00 = wx0 * wy0, w10 = ax * wy0, w01 = wx0 * ay, w11 = ax * ay;
            float c0 = w00 * wz0, c1 = w10 * wz0, c2 = w01 * wz0, c3 = w11 * wz0;
            float c4 = w00 * az,  c5 = w10 * az,  c6 = w01 * az,  c7 = w11 * az;

            float fxo = c0 * v0.x; fxo += c1 * v1.x; fxo += c2 * v2.x; fxo += c3 * v3.x;
            fxo += c4 * v4.x; fxo += c5 * v5.x; fxo += c6 * v6.x; fxo += c7 * v7.x;
            float fyo = c0 * v0.y; fyo += c1 * v1.y; fyo += c2 * v2.y; fyo += c3 * v3.y;
            fyo += c4 * v4.y; fyo += c5 * v5.y; fyo += c6 * v6.y; fyo += c7 * v7.y;
            feat[2 * l] = fxo;
            feat[2 * l + 1] = fyo;
        }

        float op = tiny_mlp<true>(feat);
        float lw = (p < 500) ? (4.0f / 3.0f) : (2.0f / 3.0f);
        lsum += fabsf(op - __ldg(gtb + p)) * lw;
    }

    s_red[tid] = lsum;
    __syncthreads();
#pragma unroll
    for (int st = 64; st > 0; st >>= 1) {
        if (tid < st) s_red[tid] += s_red[tid + st];
        __syncthreads();
    }
    if (tid == 0) g_S[b] = s_red[0] * (1.0f / (float)P);
}

// ========================== confidence path: B 2-D lines (fp32 table) ==========================
__global__ void __launch_bounds__(128, 4)
conf_kernel(const float* __restrict__ line, const float* __restrict__ table,
            LevelSpec sp, int B) {
    __shared__ float s_red[128];
    const int tid = threadIdx.x;

    const int i = blockIdx.x * 128 + tid;
    float val = 0.0f;
    if (i < B) {
        const float2* tb = (const float2*)table;
        float u0 = (__ldg(line + 2 * i) + 1.0f) * 0.5f;
        float u1 = (__ldg(line + 2 * i + 1) + 1.0f) * 0.5f;

        float feat[24];
#pragma unroll
        for (int l = 0; l < NLEV; l++) {
            const float s = sp.scale[l];
            float px = u0 * s + 0.5f, py = u1 * s + 0.5f;
            float fx = floorf(px), fy = floorf(py);
            float ax = px - fx, ay = py - fy;
            unsigned ix = (unsigned)fx, iy = (unsigned)fy;

            unsigned id[4];
            if (sp.hashed[l]) {
                unsigned hy0 = iy * PRIME1, hy1 = hy0 + PRIME1;
                id[0] = (ix ^ hy0) & HMASK; id[1] = ((ix + 1u) ^ hy0) & HMASK;
                id[2] = (ix ^ hy1) & HMASK; id[3] = ((ix + 1u) ^ hy1) & HMASK;
            } else {
                unsigned s1 = sp.res1[l];
                unsigned base = ix + iy * s1;
                id[0] = base;      id[1] = base + 1u;
                id[2] = base + s1; id[3] = base + s1 + 1u;
            }
            const unsigned off = sp.off[l];
            float2 v0 = __ldg(tb + off + id[0]);
            float2 v1 = __ldg(tb + off + id[1]);
            float2 v2 = __ldg(tb + off + id[2]);
            float2 v3 = __ldg(tb + off + id[3]);

            float wx0 = 1.0f - ax, wy0 = 1.0f - ay;
            float c0 = wx0 * wy0, c1 = ax * wy0, c2 = wx0 * ay, c3 = ax * ay;
            float fxo = c0 * v0.x; fxo += c1 * v1.x; fxo += c2 * v2.x; fxo += c3 * v3.x;
            float fyo = c0 * v0.y; fyo += c1 * v1.y; fyo += c2 * v2.y; fyo += c3 * v3.y;
            feat[2 * l] = fxo;
            feat[2 * l + 1] = fyo;
        }
        float conf = tiny_mlp<false>(feat);
        val = expf(-conf) * g_S[i] + conf;
    }

    s_red[tid] = val;
    __syncthreads();
#pragma unroll
    for (int st = 64; st > 0; st >>= 1) {
        if (tid < st) s_red[tid] += s_red[tid + st];
        __syncthreads();
    }
    if (tid == 0) g_part[blockIdx.x] = s_red[0];
}

__global__ void final_kernel(float* out, int nb, float invB) {
    __shared__ float sr[256];
    int t = threadIdx.x;
    sr[t] = (t < nb) ? g_part[t] : 0.0f;
    __syncthreads();
#pragma unroll
    for (int st = 128; st > 0; st >>= 1) {
        if (t < st) sr[t] += sr[t + st];
        __syncthreads();
    }
    if (t == 0) out[0] = sr[0] * invB;
}

// ---------- host: replicate _level_specs exactly (float64 math) ----------
static void make_specs(int D, LevelSpec* sp) {
    double f = pow(8192.0 / 16.0, 1.0 / 11.0);
    long long offset = 0;
    for (int l = 0; l < NLEV; l++) {
        double scale = 16.0 * pow(f, (double)l) - 1.0;
        long long res = (long long)ceil(scale) + 1;
        long long dense = 1;
        for (int d = 0; d < D; d++) dense *= (res + 1);
        long long params = dense;
        if (params > (1LL << 21)) params = (1LL << 21);
        params = ((params + 7) / 8) * 8;
        sp->scale[l]  = (float)scale;
        sp->off[l]    = (unsigned)offset;
        sp->res1[l]   = (unsigned)(res + 1);
        sp->hashed[l] = (dense > (1LL << 21)) ? 1u : 0u;
        offset += params;
    }
}

extern "C" void kernel_launch(void* const* d_in, const int* in_sizes, int n_in,
                              void* d_out, int out_size) {
    const float* line  = (const float*)d_in[0];
    const float* pts   = (const float*)d_in[1];
    const float* gt    = (const float*)d_in[2];
    const float* tconf = (const float*)d_in[3];
    const float* w1c   = (const float*)d_in[4];
    const float* b1c   = (const float*)d_in[5];
    const float* w2c   = (const float*)d_in[6];
    const float* b2c   = (const float*)d_in[7];
    const float* top   = (const float*)d_in[8];
    const float* w1o   = (const float*)d_in[9];
    const float* b1o   = (const float*)d_in[10];
    const float* w2o   = (const float*)d_in[11];
    const float* b2o   = (const float*)d_in[12];

    int B = in_sizes[0] / 2;
    int P = in_sizes[1] / (3 * B);
    unsigned tot3 = (unsigned)(in_sizes[8] / 2);   // entries in table_op

    LevelSpec sp3, sp2;
    make_specs(3, &sp3);
    make_specs(2, &sp2);

    // weights -> constant memory (D2D memcpy nodes; graph-capturable)
    cudaMemcpyToSymbolAsync(c_w1o, w1o, 1536 * sizeof(float), 0, cudaMemcpyDeviceToDevice);
    cudaMemcpyToSymbolAsync(c_b1o, b1o, 64 * sizeof(float),   0, cudaMemcpyDeviceToDevice);
    cudaMemcpyToSymbolAsync(c_w2o, w2o, 64 * sizeof(float),   0, cudaMemcpyDeviceToDevice);
    cudaMemcpyToSymbolAsync(c_b2o, b2o, sizeof(float),        0, cudaMemcpyDeviceToDevice);
    cudaMemcpyToSymbolAsync(c_w1c, w1c, 1536 * sizeof(float), 0, cudaMemcpyDeviceToDevice);
    cudaMemcpyToSymbolAsync(c_b1c, b1c, 64 * sizeof(float),   0, cudaMemcpyDeviceToDevice);
    cudaMemcpyToSymbolAsync(c_w2c, w2c, 64 * sizeof(float),   0, cudaMemcpyDeviceToDevice);
    cudaMemcpyToSymbolAsync(c_b2c, b2c, sizeof(float),        0, cudaMemcpyDeviceToDevice);

    // fp32 -> fp16 table conversion (2 entries per float4)
    unsigned n4 = tot3 / 2;
    convert_kernel<<<(n4 + 255) / 256, 256>>>((const float4*)top, n4);

    opacity_kernel<<<B, 128>>>(pts, gt, sp3, P);

    int nb = (B + 127) / 128;
    if (nb > 256) nb = 256;
    conf_kernel<<<nb, 128>>>(line, tconf, sp2, B);
    final_kernel<<<1, 256>>>((float*)d_out, nb, 1.0f / (float)B);
}

// round 9
// speedup vs baseline: 1.4587x; 1.3193x over previous
#include <cuda_runtime.h>
#include <cuda_fp16.h>
#include <math.h>
#include <stdint.h>

#define NLEV 12
#define PRIME1 2654435761u
#define PRIME2 805459861u
#define HMASK ((1u << 21) - 1u)

struct LevelSpec {
    float    scale[NLEV];
    unsigned off[NLEV];
    unsigned res1[NLEV];    // res + 1 (dense stride base)
    unsigned hashed[NLEV];  // 0/1
};

__device__ float g_S[8192];     // per-line mean weighted L1
__device__ float g_part[256];   // conf-kernel block partials

// fp16 copy of table_op: one u32 = half2 (feature pair) per entry.
__device__ __align__(8) unsigned g_tb_h[17700000];

// fp16 copies of opacity MLP layer-1 weights (scratch; copied into constant)
__device__ __half2 g_w1h[768];
__device__ __half2 g_b1h[32];

typedef unsigned long long u64;

// MLP weights in constant memory (filled per-launch by async D2D memcpy nodes).
__constant__ __half2 c_w1h[768];   // opacity w1, half2 pairs (units 2j,2j+1)
__constant__ __half2 c_b1h[32];
__constant__ float   c_w2o[64];
__constant__ float   c_b2o[1];
__constant__ u64     c_w1c[768];   // confidence path stays fp32 f32x2
__constant__ u64     c_b1c[32];
__constant__ float   c_w2c[64];
__constant__ float   c_b2c[1];

// ---------- packed f32x2 helpers (conf path) ----------
__device__ __forceinline__ u64 bcast_f32x2(float v) {
    u64 d;
    asm("mov.b64 %0, {%1, %1};" : "=l"(d) : "f"(v));
    return d;
}
__device__ __forceinline__ void fma_f32x2(u64& acc, u64 a, u64 b) {
    asm("fma.rn.f32x2 %0, %1, %2, %0;" : "+l"(acc) : "l"(a), "l"(b));
}
__device__ __forceinline__ float2 unpack_f32x2(u64 v) {
    float2 r;
    asm("mov.b64 {%0, %1}, %2;" : "=f"(r.x), "=f"(r.y) : "l"(v));
    return r;
}

// Opacity MLP: 24 -> 64(relu) -> 1, half2 accumulators (32 regs), constant
// weights with compile-time indices (LDCU path), fp32 output layer.
__device__ __forceinline__ float tiny_mlp_h(const float* feat) {
    __half2 acc[32];
#pragma unroll
    for (int j = 0; j < 32; j++) acc[j] = c_b1h[j];
#pragma unroll
    for (int k = 0; k < 24; k++) {
        __half2 bf = __float2half2_rn(feat[k]);
#pragma unroll
        for (int j = 0; j < 32; j++) acc[j] = __hfma2(bf, c_w1h[k * 32 + j], acc[j]);
    }
    float out = c_b2o[0];
#pragma unroll
    for (int j = 0; j < 32; j++) {
        float2 h = __half22float2(acc[j]);
        out += fmaxf(h.x, 0.0f) * c_w2o[2 * j];
        out += fmaxf(h.y, 0.0f) * c_w2o[2 * j + 1];
    }
    return out;
}

// Confidence MLP: fp32 f32x2 (unchanged, negligible cost).
__device__ __forceinline__ float tiny_mlp_c(const float* feat) {
    u64 acc[32];
#pragma unroll
    for (int j = 0; j < 32; j++) acc[j] = c_b1c[j];
#pragma unroll
    for (int k = 0; k < 24; k++) {
        u64 bf = bcast_f32x2(feat[k]);
#pragma unroll
        for (int j = 0; j < 32; j++) fma_f32x2(acc[j], bf, c_w1c[k * 32 + j]);
    }
    float out = c_b2c[0];
#pragma unroll
    for (int j = 0; j < 32; j++) {
        float2 h = unpack_f32x2(acc[j]);
        out += fmaxf(h.x, 0.0f) * c_w2c[2 * j];
        out += fmaxf(h.y, 0.0f) * c_w2c[2 * j + 1];
    }
    return out;
}

// ---------- conversion kernels (run inside the graph) ----------
__global__ void convert_kernel(const float4* __restrict__ src, unsigned n4) {
    unsigned i = blockIdx.x * blockDim.x + threadIdx.x;
    if (i < n4) {
        float4 v = __ldg(src + i);
        __half2 a = __floats2half2_rn(v.x, v.y);
        __half2 b = __floats2half2_rn(v.z, v.w);
        g_tb_h[2 * i]     = *(unsigned*)&a;
        g_tb_h[2 * i + 1] = *(unsigned*)&b;
    }
}

__global__ void convert_w_kernel(const float* __restrict__ w1, const float* __restrict__ b1) {
    int i = blockIdx.x * blockDim.x + threadIdx.x;
    if (i < 768) g_w1h[i] = __floats2half2_rn(w1[2 * i], w1[2 * i + 1]);
    if (i < 32)  g_b1h[i] = __floats2half2_rn(b1[2 * i], b1[2 * i + 1]);
}

__device__ __forceinline__ float2 h2f(unsigned raw) {
    __half2 h = *(__half2*)&raw;
    return __half22float2(h);
}
__device__ __forceinline__ float2 tb_fetch(unsigned idx) {
    return h2f(__ldg(&g_tb_h[idx]));
}

// ========================== opacity path: B*P 3-D points ==========================
__global__ void __launch_bounds__(128, 5)
opacity_kernel(const float* __restrict__ pts, const float* __restrict__ gt,
               LevelSpec sp, int P) {
    __shared__ __align__(16) float s_pts[3072];
    __shared__ float s_red[128];

    const int tid = threadIdx.x;
    const int b = blockIdx.x;
    const float* ptb = pts + (size_t)b * P * 3;
    const float* gtb = gt + (size_t)b * P;

    {
        int n4 = (3 * P) / 4;
        const float4* src4 = (const float4*)ptb;
        for (int i = tid; i < n4; i += 128) ((float4*)s_pts)[i] = src4[i];
        for (int i = 4 * n4 + tid; i < 3 * P; i += 128) s_pts[i] = ptb[i];
    }
    __syncthreads();

    float lsum = 0.0f;
    for (int p = tid; p < P; p += 128) {
        float u0 = (s_pts[3 * p + 0] + 1.0f) * 0.5f;
        float u1 = (s_pts[3 * p + 1] + 1.0f) * 0.5f;
        float u2 = (s_pts[3 * p + 2] + 1.0f) * 0.5f;

        float feat[24];
#pragma unroll
        for (int l = 0; l < NLEV; l++) {
            const float s = sp.scale[l];
            float px = u0 * s + 0.5f, py = u1 * s + 0.5f, pz = u2 * s + 0.5f;
            float fx = floorf(px), fy = floorf(py), fz = floorf(pz);
            float ax = px - fx, ay = py - fy, az = pz - fz;
            unsigned ix = (unsigned)fx, iy = (unsigned)fy, iz = (unsigned)fz;

            unsigned id[8];
            if (sp.hashed[l]) {
                unsigned hy0 = iy * PRIME1, hy1 = hy0 + PRIME1;
                unsigned hz0 = iz * PRIME2, hz1 = hz0 + PRIME2;
                unsigned a0 = ix ^ hy0, a1 = (ix + 1u) ^ hy0;
                unsigned a2 = ix ^ hy1, a3 = (ix + 1u) ^ hy1;
                id[0] = (a0 ^ hz0) & HMASK; id[1] = (a1 ^ hz0) & HMASK;
                id[2] = (a2 ^ hz0) & HMASK; id[3] = (a3 ^ hz0) & HMASK;
                id[4] = (a0 ^ hz1) & HMASK; id[5] = (a1 ^ hz1) & HMASK;
                id[6] = (a2 ^ hz1) & HMASK; id[7] = (a3 ^ hz1) & HMASK;
            } else {
                unsigned s1 = sp.res1[l], s2 = s1 * s1;
                unsigned base = ix + iy * s1 + iz * s2;
                id[0] = base;           id[1] = base + 1u;
                id[2] = base + s1;      id[3] = base + s1 + 1u;
                id[4] = base + s2;      id[5] = base + s2 + 1u;
                id[6] = base + s2 + s1; id[7] = base + s2 + s1 + 1u;
            }
            const unsigned off = sp.off[l];
            float2 v0 = tb_fetch(off + id[0]);
            float2 v1 = tb_fetch(off + id[1]);
            float2 v2 = tb_fetch(off + id[2]);
            float2 v3 = tb_fetch(off + id[3]);
            float2 v4 = tb_fetch(off + id[4]);
            float2 v5 = tb_fetch(off + id[5]);
            float2 v6 = tb_fetch(off + id[6]);
            float2 v7 = tb_fetch(off + id[7]);

            float wx0 = 1.0f - ax, wy0 = 1.0f - ay, wz0 = 1.0f - az;
            float w00 = wx0 * wy0, w10 = ax * wy0, w01 = wx0 * ay, w11 = ax * ay;
            float c0 = w00 * wz0, c1 = w10 * wz0, c2 = w01 * wz0, c3 = w11 * wz0;
            float c4 = w00 * az,  c5 = w10 * az,  c6 = w01 * az,  c7 = w11 * az;

            float fxo = c0 * v0.x; fxo += c1 * v1.x; fxo += c2 * v2.x; fxo += c3 * v3.x;
            fxo += c4 * v4.x; fxo += c5 * v5.x; fxo += c6 * v6.x; fxo += c7 * v7.x;
            float fyo = c0 * v0.y; fyo += c1 * v1.y; fyo += c2 * v2.y; fyo += c3 * v3.y;
            fyo += c4 * v4.y; fyo += c5 * v5.y; fyo += c6 * v6.y; fyo += c7 * v7.y;
            feat[2 * l] = fxo;
            feat[2 * l + 1] = fyo;
        }

        float op = tiny_mlp_h(feat);
        float lw = (p < 500) ? (4.0f / 3.0f) : (2.0f / 3.0f);
        lsum += fabsf(op - __ldg(gtb + p)) * lw;
    }

    s_red[tid] = lsum;
    __syncthreads();
#pragma unroll
    for (int st = 64; st > 0; st >>= 1) {
        if (tid < st) s_red[tid] += s_red[tid + st];
        __syncthreads();
    }
    if (tid == 0) g_S[b] = s_red[0] * (1.0f / (float)P);
}

// ========================== confidence path: B 2-D lines (fp32 table) ==========================
__global__ void __launch_bounds__(128, 4)
conf_kernel(const float* __restrict__ line, const float* __restrict__ table,
            LevelSpec sp, int B) {
    __shared__ float s_red[128];
    const int tid = threadIdx.x;

    const int i = blockIdx.x * 128 + tid;
    float val = 0.0f;
    if (i < B) {
        const float2* tb = (const float2*)table;
        float u0 = (__ldg(line + 2 * i) + 1.0f) * 0.5f;
        float u1 = (__ldg(line + 2 * i + 1) + 1.0f) * 0.5f;

        float feat[24];
#pragma unroll
        for (int l = 0; l < NLEV; l++) {
            const float s = sp.scale[l];
            float px = u0 * s + 0.5f, py = u1 * s + 0.5f;
            float fx = floorf(px), fy = floorf(py);
            float ax = px - fx, ay = py - fy;
            unsigned ix = (unsigned)fx, iy = (unsigned)fy;

            unsigned id[4];
            if (sp.hashed[l]) {
                unsigned hy0 = iy * PRIME1, hy1 = hy0 + PRIME1;
                id[0] = (ix ^ hy0) & HMASK; id[1] = ((ix + 1u) ^ hy0) & HMASK;
                id[2] = (ix ^ hy1) & HMASK; id[3] = ((ix + 1u) ^ hy1) & HMASK;
            } else {
                unsigned s1 = sp.res1[l];
                unsigned base = ix + iy * s1;
                id[0] = base;      id[1] = base + 1u;
                id[2] = base + s1; id[3] = base + s1 + 1u;
            }
            const unsigned off = sp.off[l];
            float2 v0 = __ldg(tb + off + id[0]);
            float2 v1 = __ldg(tb + off + id[1]);
            float2 v2 = __ldg(tb + off + id[2]);
            float2 v3 = __ldg(tb + off + id[3]);

            float wx0 = 1.0f - ax, wy0 = 1.0f - ay;
            float c0 = wx0 * wy0, c1 = ax * wy0, c2 = wx0 * ay, c3 = ax * ay;
            float fxo = c0 * v0.x; fxo += c1 * v1.x; fxo += c2 * v2.x; fxo += c3 * v3.x;
            float fyo = c0 * v0.y; fyo += c1 * v1.y; fyo += c2 * v2.y; fyo += c3 * v3.y;
            feat[2 * l] = fxo;
            feat[2 * l + 1] = fyo;
        }
        float conf = tiny_mlp_c(feat);
        val = expf(-conf) * g_S[i] + conf;
    }

    s_red[tid] = val;
    __syncthreads();
#pragma unroll
    for (int st = 64; st > 0; st >>= 1) {
        if (tid < st) s_red[tid] += s_red[tid + st];
        __syncthreads();
    }
    if (tid == 0) g_part[blockIdx.x] = s_red[0];
}

__global__ void final_kernel(float* out, int nb, float invB) {
    __shared__ float sr[256];
    int t = threadIdx.x;
    sr[t] = (t < nb) ? g_part[t] : 0.0f;
    __syncthreads();
#pragma unroll
    for (int st = 128; st > 0; st >>= 1) {
        if (t < st) sr[t] += sr[t + st];
        __syncthreads();
    }
    if (t == 0) out[0] = sr[0] * invB;
}

// ---------- host: replicate _level_specs exactly (float64 math) ----------
static void make_specs(int D, LevelSpec* sp) {
    double f = pow(8192.0 / 16.0, 1.0 / 11.0);
    long long offset = 0;
    for (int l = 0; l < NLEV; l++) {
        double scale = 16.0 * pow(f, (double)l) - 1.0;
        long long res = (long long)ceil(scale) + 1;
        long long dense = 1;
        for (int d = 0; d < D; d++) dense *= (res + 1);
        long long params = dense;
        if (params > (1LL << 21)) params = (1LL << 21);
        params = ((params + 7) / 8) * 8;
        sp->scale[l]  = (float)scale;
        sp->off[l]    = (unsigned)offset;
        sp->res1[l]   = (unsigned)(res + 1);
        sp->hashed[l] = (dense > (1LL << 21)) ? 1u : 0u;
        offset += params;
    }
}

extern "C" void kernel_launch(void* const* d_in, const int* in_sizes, int n_in,
                              void* d_out, int out_size) {
    const float* line  = (const float*)d_in[0];
    const float* pts   = (const float*)d_in[1];
    const float* gt    = (const float*)d_in[2];
    const float* tconf = (const float*)d_in[3];
    const float* w1c   = (const float*)d_in[4];
    const float* b1c   = (const float*)d_in[5];
    const float* w2c   = (const float*)d_in[6];
    const float* b2c   = (const float*)d_in[7];
    const float* top   = (const float*)d_in[8];
    const float* w1o   = (const float*)d_in[9];
    const float* b1o   = (const float*)d_in[10];
    const float* w2o   = (const float*)d_in[11];
    const float* b2o   = (const float*)d_in[12];

    int B = in_sizes[0] / 2;
    int P = in_sizes[1] / (3 * B);
    unsigned tot3 = (unsigned)(in_sizes[8] / 2);   // entries in table_op

    LevelSpec sp3, sp2;
    make_specs(3, &sp3);
    make_specs(2, &sp2);

    // confidence weights (fp32) -> constant
    cudaMemcpyToSymbolAsync(c_w1c, w1c, 1536 * sizeof(float), 0, cudaMemcpyDeviceToDevice);
    cudaMemcpyToSymbolAsync(c_b1c, b1c, 64 * sizeof(float),   0, cudaMemcpyDeviceToDevice);
    cudaMemcpyToSymbolAsync(c_w2c, w2c, 64 * sizeof(float),   0, cudaMemcpyDeviceToDevice);
    cudaMemcpyToSymbolAsync(c_b2c, b2c, sizeof(float),        0, cudaMemcpyDeviceToDevice);
    // opacity fp32 output-layer weights -> constant
    cudaMemcpyToSymbolAsync(c_w2o, w2o, 64 * sizeof(float),   0, cudaMemcpyDeviceToDevice);
    cudaMemcpyToSymbolAsync(c_b2o, b2o, sizeof(float),        0, cudaMemcpyDeviceToDevice);

    // opacity layer-1 weights fp32 -> fp16 scratch, then into constant
    convert_w_kernel<<<3, 256>>>(w1o, b1o);
    void *p_w1h = nullptr, *p_b1h = nullptr;
    cudaGetSymbolAddress(&p_w1h, g_w1h);
    cudaGetSymbolAddress(&p_b1h, g_b1h);
    cudaMemcpyToSymbolAsync(c_w1h, p_w1h, 768 * sizeof(__half2), 0, cudaMemcpyDeviceToDevice);
    cudaMemcpyToSymbolAsync(c_b1h, p_b1h, 32 * sizeof(__half2),  0, cudaMemcpyDeviceToDevice);

    // fp32 -> fp16 table conversion (2 entries per float4)
    unsigned n4 = tot3 / 2;
    convert_kernel<<<(n4 + 255) / 256, 256>>>((const float4*)top, n4);

    opacity_kernel<<<B, 128>>>(pts, gt, sp3, P);

    int nb = (B + 127) / 128;
    if (nb > 256) nb = 256;
    conf_kernel<<<nb, 128>>>(line, tconf, sp2, B);
    final_kernel<<<1, 256>>>((float*)d_out, nb, 1.0f / (float)B);
}

// round 10
// speedup vs baseline: 1.5043x; 1.0313x over previous
#include <cuda_runtime.h>
#include <cuda_fp16.h>
#include <math.h>
#include <stdint.h>

#define NLEV 12
#define PRIME1 2654435761u
#define PRIME2 805459861u
#define HMASK ((1u << 21) - 1u)

struct LevelSpec {
    float    scale[NLEV];
    unsigned off[NLEV];
    unsigned res1[NLEV];    // res + 1 (dense stride base)
    unsigned hashed[NLEV];  // 0/1
};

__device__ float g_S[8192];     // per-line mean weighted L1
__device__ float g_part[256];   // conf-kernel block partials

// fp16 copy of table_op: one u32 = half2 (feature pair) per entry.
__device__ __align__(8) unsigned g_tb_h[17700000];

// fp16 copies of opacity MLP layer-1 weights (scratch; copied into constant)
__device__ __half2 g_w1h[768];
__device__ __half2 g_b1h[32];

typedef unsigned long long u64;

// MLP weights in constant memory (filled per-launch by async D2D memcpy nodes).
__constant__ __half2 c_w1h[768];   // opacity w1, half2 pairs (units 2j,2j+1)
__constant__ __half2 c_b1h[32];
__constant__ float   c_w2o[64];
__constant__ float   c_b2o[1];
__constant__ u64     c_w1c[768];   // confidence path stays fp32 f32x2
__constant__ u64     c_b1c[32];
__constant__ float   c_w2c[64];
__constant__ float   c_b2c[1];

// ---------- packed f32x2 helpers (conf path) ----------
__device__ __forceinline__ u64 bcast_f32x2(float v) {
    u64 d;
    asm("mov.b64 %0, {%1, %1};" : "=l"(d) : "f"(v));
    return d;
}
__device__ __forceinline__ void fma_f32x2(u64& acc, u64 a, u64 b) {
    asm("fma.rn.f32x2 %0, %1, %2, %0;" : "+l"(acc) : "l"(a), "l"(b));
}
__device__ __forceinline__ float2 unpack_f32x2(u64 v) {
    float2 r;
    asm("mov.b64 {%0, %1}, %2;" : "=f"(r.x), "=f"(r.y) : "l"(v));
    return r;
}

// Opacity MLP: 24 -> 64(relu) -> 1. feat arrives as 12 half2 (level pairs).
// half2 accumulators (32 regs), constant weights, fully unrolled (LDCU path).
__device__ __forceinline__ float tiny_mlp_h(const __half2* feat2) {
    __half2 acc[32];
#pragma unroll
    for (int j = 0; j < 32; j++) acc[j] = c_b1h[j];
#pragma unroll
    for (int l = 0; l < 12; l++) {
        __half2 f = feat2[l];
        __half2 blo = __low2half2(f);    // input 2l broadcast
        __half2 bhi = __high2half2(f);   // input 2l+1 broadcast
#pragma unroll
        for (int j = 0; j < 32; j++) acc[j] = __hfma2(blo, c_w1h[(2 * l) * 32 + j], acc[j]);
#pragma unroll
        for (int j = 0; j < 32; j++) acc[j] = __hfma2(bhi, c_w1h[(2 * l + 1) * 32 + j], acc[j]);
    }
    float out = c_b2o[0];
#pragma unroll
    for (int j = 0; j < 32; j++) {
        float2 h = __half22float2(acc[j]);
        out += fmaxf(h.x, 0.0f) * c_w2o[2 * j];
        out += fmaxf(h.y, 0.0f) * c_w2o[2 * j + 1];
    }
    return out;
}

// Confidence MLP: fp32 f32x2 (unchanged, negligible cost).
__device__ __forceinline__ float tiny_mlp_c(const float* feat) {
    u64 acc[32];
#pragma unroll
    for (int j = 0; j < 32; j++) acc[j] = c_b1c[j];
#pragma unroll
    for (int k = 0; k < 24; k++) {
        u64 bf = bcast_f32x2(feat[k]);
#pragma unroll
        for (int j = 0; j < 32; j++) fma_f32x2(acc[j], bf, c_w1c[k * 32 + j]);
    }
    float out = c_b2c[0];
#pragma unroll
    for (int j = 0; j < 32; j++) {
        float2 h = unpack_f32x2(acc[j]);
        out += fmaxf(h.x, 0.0f) * c_w2c[2 * j];
        out += fmaxf(h.y, 0.0f) * c_w2c[2 * j + 1];
    }
    return out;
}

// ---------- conversion kernels (run inside the graph) ----------
__global__ void convert_kernel(const float4* __restrict__ src, unsigned n4) {
    unsigned i = blockIdx.x * blockDim.x + threadIdx.x;
    if (i < n4) {
        float4 v = __ldg(src + i);
        __half2 a = __floats2half2_rn(v.x, v.y);
        __half2 b = __floats2half2_rn(v.z, v.w);
        g_tb_h[2 * i]     = *(unsigned*)&a;
        g_tb_h[2 * i + 1] = *(unsigned*)&b;
    }
}

__global__ void convert_w_kernel(const float* __restrict__ w1, const float* __restrict__ b1) {
    int i = blockIdx.x * blockDim.x + threadIdx.x;
    if (i < 768) g_w1h[i] = __floats2half2_rn(w1[2 * i], w1[2 * i + 1]);
    if (i < 32)  g_b1h[i] = __floats2half2_rn(b1[2 * i], b1[2 * i + 1]);
}

__device__ __forceinline__ __half2 tb_fetch_h(unsigned idx) {
    unsigned raw = __ldg(&g_tb_h[idx]);
    return *(__half2*)&raw;
}

// ========================== opacity path: B*P 3-D points ==========================
__global__ void __launch_bounds__(128, 6)
opacity_kernel(const float* __restrict__ pts, const float* __restrict__ gt,
               LevelSpec sp, int P) {
    __shared__ __align__(16) float s_pts[3072];
    __shared__ float s_red[128];

    const int tid = threadIdx.x;
    const int b = blockIdx.x;
    const float* ptb = pts + (size_t)b * P * 3;
    const float* gtb = gt + (size_t)b * P;

    {
        int n4 = (3 * P) / 4;
        const float4* src4 = (const float4*)ptb;
        for (int i = tid; i < n4; i += 128) ((float4*)s_pts)[i] = src4[i];
        for (int i = 4 * n4 + tid; i < 3 * P; i += 128) s_pts[i] = ptb[i];
    }
    __syncthreads();

    float lsum = 0.0f;
    for (int p = tid; p < P; p += 128) {
        float u0 = (s_pts[3 * p + 0] + 1.0f) * 0.5f;
        float u1 = (s_pts[3 * p + 1] + 1.0f) * 0.5f;
        float u2 = (s_pts[3 * p + 2] + 1.0f) * 0.5f;

        __half2 feat2[12];
#pragma unroll
        for (int l = 0; l < NLEV; l++) {
            const float s = sp.scale[l];
            float px = u0 * s + 0.5f, py = u1 * s + 0.5f, pz = u2 * s + 0.5f;
            float fx = floorf(px), fy = floorf(py), fz = floorf(pz);
            float ax = px - fx, ay = py - fy, az = pz - fz;
            unsigned ix = (unsigned)fx, iy = (unsigned)fy, iz = (unsigned)fz;

            unsigned id[8];
            if (sp.hashed[l]) {
                unsigned hy0 = iy * PRIME1, hy1 = hy0 + PRIME1;
                unsigned hz0 = iz * PRIME2, hz1 = hz0 + PRIME2;
                unsigned a0 = ix ^ hy0, a1 = (ix + 1u) ^ hy0;
                unsigned a2 = ix ^ hy1, a3 = (ix + 1u) ^ hy1;
                id[0] = (a0 ^ hz0) & HMASK; id[1] = (a1 ^ hz0) & HMASK;
                id[2] = (a2 ^ hz0) & HMASK; id[3] = (a3 ^ hz0) & HMASK;
                id[4] = (a0 ^ hz1) & HMASK; id[5] = (a1 ^ hz1) & HMASK;
                id[6] = (a2 ^ hz1) & HMASK; id[7] = (a3 ^ hz1) & HMASK;
            } else {
                unsigned s1 = sp.res1[l], s2 = s1 * s1;
                unsigned base = ix + iy * s1 + iz * s2;
                id[0] = base;           id[1] = base + 1u;
                id[2] = base + s1;      id[3] = base + s1 + 1u;
                id[4] = base + s2;      id[5] = base + s2 + 1u;
                id[6] = base + s2 + s1; id[7] = base + s2 + s1 + 1u;
            }
            const unsigned off = sp.off[l];
            __half2 v0 = tb_fetch_h(off + id[0]);
            __half2 v1 = tb_fetch_h(off + id[1]);
            __half2 v2 = tb_fetch_h(off + id[2]);
            __half2 v3 = tb_fetch_h(off + id[3]);
            __half2 v4 = tb_fetch_h(off + id[4]);
            __half2 v5 = tb_fetch_h(off + id[5]);
            __half2 v6 = tb_fetch_h(off + id[6]);
            __half2 v7 = tb_fetch_h(off + id[7]);

            float wx0 = 1.0f - ax, wy0 = 1.0f - ay, wz0 = 1.0f - az;
            float w00 = wx0 * wy0, w10 = ax * wy0, w01 = wx0 * ay, w11 = ax * ay;

            __half2 f = __hmul2(__float2half2_rn(w00 * wz0), v0);
            f = __hfma2(__float2half2_rn(w10 * wz0), v1, f);
            f = __hfma2(__float2half2_rn(w01 * wz0), v2, f);
            f = __hfma2(__float2half2_rn(w11 * wz0), v3, f);
            f = __hfma2(__float2half2_rn(w00 * az),  v4, f);
            f = __hfma2(__float2half2_rn(w10 * az),  v5, f);
            f = __hfma2(__float2half2_rn(w01 * az),  v6, f);
            f = __hfma2(__float2half2_rn(w11 * az),  v7, f);
            feat2[l] = f;
        }

        float op = tiny_mlp_h(feat2);
        float lw = (p < 500) ? (4.0f / 3.0f) : (2.0f / 3.0f);
        lsum += fabsf(op - __ldg(gtb + p)) * lw;
    }

    s_red[tid] = lsum;
    __syncthreads();
#pragma unroll
    for (int st = 64; st > 0; st >>= 1) {
        if (tid < st) s_red[tid] += s_red[tid + st];
        __syncthreads();
    }
    if (tid == 0) g_S[b] = s_red[0] * (1.0f / (float)P);
}

// ========================== confidence path: B 2-D lines (fp32 table) ==========================
__global__ void __launch_bounds__(128, 4)
conf_kernel(const float* __restrict__ line, const float* __restrict__ table,
            LevelSpec sp, int B) {
    __shared__ float s_red[128];
    const int tid = threadIdx.x;

    const int i = blockIdx.x * 128 + tid;
    float val = 0.0f;
    if (i < B) {
        const float2* tb = (const float2*)table;
        float u0 = (__ldg(line + 2 * i) + 1.0f) * 0.5f;
        float u1 = (__ldg(line + 2 * i + 1) + 1.0f) * 0.5f;

        float feat[24];
#pragma unroll
        for (int l = 0; l < NLEV; l++) {
            const float s = sp.scale[l];
            float px = u0 * s + 0.5f, py = u1 * s + 0.5f;
            float fx = floorf(px), fy = floorf(py);
            float ax = px - fx, ay = py - fy;
            unsigned ix = (unsigned)fx, iy = (unsigned)fy;

            unsigned id[4];
            if (sp.hashed[l]) {
                unsigned hy0 = iy * PRIME1, hy1 = hy0 + PRIME1;
                id[0] = (ix ^ hy0) & HMASK; id[1] = ((ix + 1u) ^ hy0) & HMASK;
                id[2] = (ix ^ hy1) & HMASK; id[3] = ((ix + 1u) ^ hy1) & HMASK;
            } else {
                unsigned s1 = sp.res1[l];
                unsigned base = ix + iy * s1;
                id[0] = base;      id[1] = base + 1u;
                id[2] = base + s1; id[3] = base + s1 + 1u;
            }
            const unsigned off = sp.off[l];
            float2 v0 = __ldg(tb + off + id[0]);
            float2 v1 = __ldg(tb + off + id[1]);
            float2 v2 = __ldg(tb + off + id[2]);
            float2 v3 = __ldg(tb + off + id[3]);

            float wx0 = 1.0f - ax, wy0 = 1.0f - ay;
            float c0 = wx0 * wy0, c1 = ax * wy0, c2 = wx0 * ay, c3 = ax * ay;
            float fxo = c0 * v0.x; fxo += c1 * v1.x; fxo += c2 * v2.x; fxo += c3 * v3.x;
            float fyo = c0 * v0.y; fyo += c1 * v1.y; fyo += c2 * v2.y; fyo += c3 * v3.y;
            feat[2 * l] = fxo;
            feat[2 * l + 1] = fyo;
        }
        float conf = tiny_mlp_c(feat);
        val = expf(-conf) * g_S[i] + conf;
    }

    s_red[tid] = val;
    __syncthreads();
#pragma unroll
    for (int st = 64; st > 0; st >>= 1) {
        if (tid < st) s_red[tid] += s_red[tid + st];
        __syncthreads();
    }
    if (tid == 0) g_part[blockIdx.x] = s_red[0];
}

__global__ void final_kernel(float* out, int nb, float invB) {
    __shared__ float sr[256];
    int t = threadIdx.x;
    sr[t] = (t < nb) ? g_part[t] : 0.0f;
    __syncthreads();
#pragma unroll
    for (int st = 128; st > 0; st >>= 1) {
        if (t < st) sr[t] += sr[t + st];
        __syncthreads();
    }
    if (t == 0) out[0] = sr[0] * invB;
}

// ---------- host: replicate _level_specs exactly (float64 math) ----------
static void make_specs(int D, LevelSpec* sp) {
    double f = pow(8192.0 / 16.0, 1.0 / 11.0);
    long long offset = 0;
    for (int l = 0; l < NLEV; l++) {
        double scale = 16.0 * pow(f, (double)l) - 1.0;
        long long res = (long long)ceil(scale) + 1;
        long long dense = 1;
        for (int d = 0; d < D; d++) dense *= (res + 1);
        long long params = dense;
        if (params > (1LL << 21)) params = (1LL << 21);
        params = ((params + 7) / 8) * 8;
        sp->scale[l]  = (float)scale;
        sp->off[l]    = (unsigned)offset;
        sp->res1[l]   = (unsigned)(res + 1);
        sp->hashed[l] = (dense > (1LL << 21)) ? 1u : 0u;
        offset += params;
    }
}

extern "C" void kernel_launch(void* const* d_in, const int* in_sizes, int n_in,
                              void* d_out, int out_size) {
    const float* line  = (const float*)d_in[0];
    const float* pts   = (const float*)d_in[1];
    const float* gt    = (const float*)d_in[2];
    const float* tconf = (const float*)d_in[3];
    const float* w1c   = (const float*)d_in[4];
    const float* b1c   = (const float*)d_in[5];
    const float* w2c   = (const float*)d_in[6];
    const float* b2c   = (const float*)d_in[7];
    const float* top   = (const float*)d_in[8];
    const float* w1o   = (const float*)d_in[9];
    const float* b1o   = (const float*)d_in[10];
    const float* w2o   = (const float*)d_in[11];
    const float* b2o   = (const float*)d_in[12];

    int B = in_sizes[0] / 2;
    int P = in_sizes[1] / (3 * B);
    unsigned tot3 = (unsigned)(in_sizes[8] / 2);   // entries in table_op

    LevelSpec sp3, sp2;
    make_specs(3, &sp3);
    make_specs(2, &sp2);

    // confidence weights (fp32) -> constant
    cudaMemcpyToSymbolAsync(c_w1c, w1c, 1536 * sizeof(float), 0, cudaMemcpyDeviceToDevice);
    cudaMemcpyToSymbolAsync(c_b1c, b1c, 64 * sizeof(float),   0, cudaMemcpyDeviceToDevice);
    cudaMemcpyToSymbolAsync(c_w2c, w2c, 64 * sizeof(float),   0, cudaMemcpyDeviceToDevice);
    cudaMemcpyToSymbolAsync(c_b2c, b2c, sizeof(float),        0, cudaMemcpyDeviceToDevice);
    // opacity fp32 output-layer weights -> constant
    cudaMemcpyToSymbolAsync(c_w2o, w2o, 64 * sizeof(float),   0, cudaMemcpyDeviceToDevice);
    cudaMemcpyToSymbolAsync(c_b2o, b2o, sizeof(float),        0, cudaMemcpyDeviceToDevice);

    // opacity layer-1 weights fp32 -> fp16 scratch, then into constant
    convert_w_kernel<<<3, 256>>>(w1o, b1o);
    void *p_w1h = nullptr, *p_b1h = nullptr;
    cudaGetSymbolAddress(&p_w1h, g_w1h);
    cudaGetSymbolAddress(&p_b1h, g_b1h);
    cudaMemcpyToSymbolAsync(c_w1h, p_w1h, 768 * sizeof(__half2), 0, cudaMemcpyDeviceToDevice);
    cudaMemcpyToSymbolAsync(c_b1h, p_b1h, 32 * sizeof(__half2),  0, cudaMemcpyDeviceToDevice);

    // fp32 -> fp16 table conversion (2 entries per float4)
    unsigned n4 = tot3 / 2;
    convert_kernel<<<(n4 + 255) / 256, 256>>>((const float4*)top, n4);

    opacity_kernel<<<B, 128>>>(pts, gt, sp3, P);

    int nb = (B + 127) / 128;
    if (nb > 256) nb = 256;
    conf_kernel<<<nb, 128>>>(line, tconf, sp2, B);
    final_kernel<<<1, 256>>>((float*)d_out, nb, 1.0f / (float)B);
}